// round 3
// baseline (speedup 1.0000x reference)
#include <cuda_runtime.h>

#define B   8
#define D   512
#define L   4096
#define NH  8
#define HD  64
#define LP1 4097
#define ATT_SCALE 0.125f   // 1/sqrt(64)

// Scratch (device globals: no runtime allocation allowed)
__device__ float g_q[B * LP1 * D];
__device__ float g_k[B * LP1 * D];
__device__ float g_v[B * LP1 * D];
__device__ float g_att[B * L * D];   // (b, l, d) row-major
__device__ float g_attr[B * D];

// ---------------------------------------------------------------------------
// QKV projection for the L "node" tokens.
//   out[b][l][j] = sum_d x[b][d][l] * W[d][j]
// x is (B, D, L) so A is K-major with contiguous l -> coalesced loads.
// 64x64 output tile, BK=16, 256 threads, 4x4 per-thread.
// grid: (B*L/64, D/64, 3)
// ---------------------------------------------------------------------------
__global__ void qkv_gemm(const float* __restrict__ x,
                         const float* __restrict__ Wq,
                         const float* __restrict__ Wk,
                         const float* __restrict__ Wv) {
    __shared__ float As[16][64];
    __shared__ float Ws[16][64];

    int z = blockIdx.z;
    const float* W = (z == 0) ? Wq : (z == 1) ? Wk : Wv;
    float* out = (z == 0) ? g_q : (z == 1) ? g_k : g_v;

    int m0 = blockIdx.x * 64;          // global row index (b*L + l)
    int b  = m0 >> 12;                 // L = 4096
    int l0 = m0 & (L - 1);
    int j0 = blockIdx.y * 64;

    const float* xb = x + (size_t)b * D * L;
    int tid = threadIdx.x;
    int tx = tid & 15, ty = tid >> 4;

    float acc[4][4] = {};

    for (int kt = 0; kt < D; kt += 16) {
        #pragma unroll
        for (int r = 0; r < 4; r++) {
            int i  = tid + r * 256;
            int li = i & 63, di = i >> 6;
            As[di][li] = xb[(size_t)(kt + di) * L + l0 + li];
            Ws[di][li] = W[(size_t)(kt + di) * D + j0 + li];
        }
        __syncthreads();
        #pragma unroll
        for (int kk = 0; kk < 16; kk++) {
            float a[4], w[4];
            #pragma unroll
            for (int i = 0; i < 4; i++) a[i] = As[kk][ty * 4 + i];
            #pragma unroll
            for (int j = 0; j < 4; j++) w[j] = Ws[kk][tx * 4 + j];
            #pragma unroll
            for (int i = 0; i < 4; i++)
                #pragma unroll
                for (int j = 0; j < 4; j++)
                    acc[i][j] += a[i] * w[j];
        }
        __syncthreads();
    }

    float* ob = out + (size_t)b * LP1 * D;
    #pragma unroll
    for (int i = 0; i < 4; i++) {
        int l = l0 + ty * 4 + i;
        #pragma unroll
        for (int j = 0; j < 4; j++)
            ob[(size_t)l * D + j0 + tx * 4 + j] = acc[i][j];
    }
}

// ---------------------------------------------------------------------------
// QKV projection for the relay token (row l = L), input y (B, D).
// grid: (3, B), block: 512
// ---------------------------------------------------------------------------
__global__ void qkv_relay(const float* __restrict__ y,
                          const float* __restrict__ Wq,
                          const float* __restrict__ Wk,
                          const float* __restrict__ Wv) {
    int z = blockIdx.x, b = blockIdx.y;
    const float* W = (z == 0) ? Wq : (z == 1) ? Wk : Wv;
    float* out = (z == 0) ? g_q : (z == 1) ? g_k : g_v;

    __shared__ float sy[D];
    int t = threadIdx.x;
    sy[t] = y[b * D + t];
    __syncthreads();

    float s = 0.f;
    for (int d = 0; d < D; d++) s += sy[d] * W[(size_t)d * D + t];
    out[(size_t)b * LP1 * D + (size_t)L * D + t] = s;
}

// ---------------------------------------------------------------------------
// Local windowed attention: per (b, l) block, warp w = head.
// 4 candidate keys per token: l-1, l, l+1 (zero-padded -> score exactly 0),
// plus the relay token (index L). Softmax over the 4 scores.
// grid: B*L blocks, 256 threads (8 warps).
// ---------------------------------------------------------------------------
__global__ void local_attn() {
    int m = blockIdx.x;
    int b = m >> 12, l = m & (L - 1);
    int head = threadIdx.x >> 5;
    int lane = threadIdx.x & 31;

    const float* qb = g_q + (size_t)b * LP1 * D;
    const float* kb = g_k + (size_t)b * LP1 * D;
    const float* vb = g_v + (size_t)b * LP1 * D;

    int hoff = head * HD + lane * 2;
    float2 qv = *(const float2*)(qb + (size_t)l * D + hoff);

    float s[4];
    int   lk[4];
    bool  valid[4];
    #pragma unroll
    for (int w = 0; w < 3; w++) {
        lk[w] = l - 1 + w;
        valid[w] = ((unsigned)lk[w] < (unsigned)L);
    }
    lk[3] = L; valid[3] = true;

    #pragma unroll
    for (int w = 0; w < 4; w++) {
        float sv = 0.f;
        if (valid[w]) {   // uniform across the warp
            float2 kv = *(const float2*)(kb + (size_t)lk[w] * D + hoff);
            sv = qv.x * kv.x + qv.y * kv.y;
            #pragma unroll
            for (int o = 16; o > 0; o >>= 1)
                sv += __shfl_xor_sync(0xffffffffu, sv, o);
            sv *= ATT_SCALE;
        }
        s[w] = sv;        // padded key contributes score 0 (matches ref zero-pad)
    }

    float mx = fmaxf(fmaxf(s[0], s[1]), fmaxf(s[2], s[3]));
    float e[4], denom = 0.f;
    #pragma unroll
    for (int w = 0; w < 4; w++) { e[w] = expf(s[w] - mx); denom += e[w]; }
    float inv = 1.f / denom;

    float2 acc = make_float2(0.f, 0.f);
    #pragma unroll
    for (int w = 0; w < 4; w++) {
        if (valid[w]) {   // padded value vector is zero
            float2 vv = *(const float2*)(vb + (size_t)lk[w] * D + hoff);
            float a = e[w] * inv;
            acc.x += a * vv.x;
            acc.y += a * vv.y;
        }
    }
    *(float2*)(g_att + ((size_t)b * L + l) * D + hoff) = acc;
}

// ---------------------------------------------------------------------------
// Ring output projection: nodes[b][e][l] = sum_d att[b][l][d]*WO[d][e] + bO[e]
// Output written transposed (e-major, contiguous l) to match (B, D, L, 1).
// grid: (L/64, D/64, B), 256 threads.
// ---------------------------------------------------------------------------
__global__ void ring_gemm(const float* __restrict__ WO,
                          const float* __restrict__ bO,
                          float* __restrict__ out) {
    __shared__ float As[16][65];   // [d][l], padded
    __shared__ float Ws[16][64];   // [d][e]

    int b  = blockIdx.z;
    int l0 = blockIdx.x * 64;
    int e0 = blockIdx.y * 64;
    const float* ab = g_att + (size_t)b * L * D;

    int tid = threadIdx.x;
    int tx = tid & 15, ty = tid >> 4;
    float acc[4][4] = {};

    for (int kt = 0; kt < D; kt += 16) {
        #pragma unroll
        for (int r = 0; r < 4; r++) {
            int i = tid + r * 256;
            int di = i & 15, li = i >> 4;
            As[di][li] = ab[(size_t)(l0 + li) * D + kt + di];
            int jj = i & 63, dj = i >> 6;
            Ws[dj][jj] = WO[(size_t)(kt + dj) * D + e0 + jj];
        }
        __syncthreads();
        #pragma unroll
        for (int kk = 0; kk < 16; kk++) {
            float a[4], w[4];
            #pragma unroll
            for (int j = 0; j < 4; j++) a[j] = As[kk][tx * 4 + j];  // l
            #pragma unroll
            for (int i = 0; i < 4; i++) w[i] = Ws[kk][ty * 4 + i];  // e
            #pragma unroll
            for (int i = 0; i < 4; i++)
                #pragma unroll
                for (int j = 0; j < 4; j++)
                    acc[i][j] += w[i] * a[j];
        }
        __syncthreads();
    }

    #pragma unroll
    for (int i = 0; i < 4; i++) {
        int e = e0 + ty * 4 + i;
        float bias = bO[e];
        #pragma unroll
        for (int j = 0; j < 4; j++) {
            int l = l0 + tx * 4 + j;
            out[(size_t)b * D * L + (size_t)e * L + l] = acc[i][j] + bias;
        }
    }
}

// ---------------------------------------------------------------------------
// Relay attention: relay query attends over all L+1 keys of its head.
// grid: (NH, B), 256 threads.
// ---------------------------------------------------------------------------
__global__ void relay_attn() {
    int n = blockIdx.x, b = blockIdx.y;
    __shared__ float sq[HD];
    __shared__ float sc[LP1];
    __shared__ float red[256];
    __shared__ float pacc[4][64];

    int tid = threadIdx.x;
    const float* qb = g_q + (size_t)b * LP1 * D;
    const float* kb = g_k + (size_t)b * LP1 * D;
    const float* vb = g_v + (size_t)b * LP1 * D;
    int hoff = n * HD;

    if (tid < HD) sq[tid] = qb[(size_t)L * D + hoff + tid];
    __syncthreads();

    // Phase 1: scores + local max
    float lmax = -1e30f;
    for (int l = tid; l < LP1; l += 256) {
        const float* kr = kb + (size_t)l * D + hoff;
        float dot = 0.f;
        #pragma unroll 8
        for (int d = 0; d < HD; d++) dot += sq[d] * kr[d];
        dot *= ATT_SCALE;
        sc[l] = dot;
        lmax = fmaxf(lmax, dot);
    }
    red[tid] = lmax; __syncthreads();
    for (int s = 128; s > 0; s >>= 1) {
        if (tid < s) red[tid] = fmaxf(red[tid], red[tid + s]);
        __syncthreads();
    }
    float mx = red[0];
    __syncthreads();

    // Phase 2: exp + sum
    float lsum = 0.f;
    for (int l = tid; l < LP1; l += 256) {
        float e = expf(sc[l] - mx);
        sc[l] = e;
        lsum += e;
    }
    red[tid] = lsum; __syncthreads();
    for (int s = 128; s > 0; s >>= 1) {
        if (tid < s) red[tid] += red[tid + s];
        __syncthreads();
    }
    float inv = 1.f / red[0];
    __syncthreads();

    // Phase 3: weighted V sum; threads: d = tid&63, group g = tid>>6
    int d = tid & 63, g = tid >> 6;
    float part = 0.f;
    for (int l = g; l < LP1; l += 4)
        part += sc[l] * vb[(size_t)l * D + hoff + d];
    pacc[g][d] = part;
    __syncthreads();
    if (tid < 64) {
        float tot = (pacc[0][tid] + pacc[1][tid] + pacc[2][tid] + pacc[3][tid]) * inv;
        g_attr[b * D + hoff + tid] = tot;
    }
}

// ---------------------------------------------------------------------------
// Relay output projection: relay[b][e] = sum_d attr[b][d]*WOs[d][e] + bOs[e]
// grid: B, block: 512. Written after the nodes region in d_out.
// ---------------------------------------------------------------------------
__global__ void relay_out(const float* __restrict__ WOs,
                          const float* __restrict__ bOs,
                          float* __restrict__ out) {
    int b = blockIdx.x;
    __shared__ float sa[D];
    int t = threadIdx.x;
    sa[t] = g_attr[b * D + t];
    __syncthreads();
    float s = bOs[t];
    for (int d = 0; d < D; d++) s += sa[d] * WOs[(size_t)d * D + t];
    out[(size_t)B * D * L + b * D + t] = s;
}

// ---------------------------------------------------------------------------
extern "C" void kernel_launch(void* const* d_in, const int* in_sizes, int n_in,
                              void* d_out, int out_size) {
    const float* x       = (const float*)d_in[0];
    const float* y       = (const float*)d_in[1];
    const float* Wq      = (const float*)d_in[2];
    const float* Wk      = (const float*)d_in[3];
    const float* Wv      = (const float*)d_in[4];
    const float* WO_ring = (const float*)d_in[5];
    const float* bO_ring = (const float*)d_in[6];
    const float* WO_star = (const float*)d_in[7];
    const float* bO_star = (const float*)d_in[8];
    float* out = (float*)d_out;

    qkv_gemm <<<dim3(B * L / 64, D / 64, 3), 256>>>(x, Wq, Wk, Wv);
    qkv_relay<<<dim3(3, B), D>>>(y, Wq, Wk, Wv);
    local_attn<<<B * L, 256>>>();
    ring_gemm<<<dim3(L / 64, D / 64, B), 256>>>(WO_ring, bO_ring, out);
    relay_attn<<<dim3(NH, B), 256>>>();
    relay_out<<<B, D>>>(WO_star, bO_star, out);
}

// round 5
// speedup vs baseline: 1.4107x; 1.4107x over previous
#include <cuda_runtime.h>

#define B   8
#define D   512
#define L   4096
#define NH  8
#define HD  64
#define LP1 4097
#define ATT_SCALE 0.125f   // 1/sqrt(64)

// Scratch (device globals: no runtime allocation allowed)
__device__ float g_q[B * LP1 * D];
__device__ float g_k[B * LP1 * D];
__device__ float g_v[B * LP1 * D];
__device__ float g_att[B * L * D];   // (b, l, d) row-major
__device__ float g_attr[B * D];

// ---------------------------------------------------------------------------
// QKV projection for the L "node" tokens.
//   out[b][l][j] = sum_d x[b][d][l] * W[d][j]
// 128x128 tile, BK=16, 256 threads, 8x8 per-thread, double-buffered smem.
// grid: (B*L/128, D/128, 3)
// ---------------------------------------------------------------------------
__global__ void __launch_bounds__(256, 2)
qkv_gemm(const float* __restrict__ x,
         const float* __restrict__ Wq,
         const float* __restrict__ Wk,
         const float* __restrict__ Wv) {
    __shared__ float As[2][16][128];
    __shared__ float Ws[2][16][128];

    int z = blockIdx.z;
    const float* W = (z == 0) ? Wq : (z == 1) ? Wk : Wv;
    float* out = (z == 0) ? g_q : (z == 1) ? g_k : g_v;

    int m0 = blockIdx.x * 128;         // global row index (b*L + l)
    int b  = m0 >> 12;                 // L = 4096
    int l0 = m0 & (L - 1);
    int j0 = blockIdx.y * 128;

    const float* xb = x + (size_t)b * D * L;
    int tid = threadIdx.x;
    int tx = tid & 15, ty = tid >> 4;

    // Loader mapping: 512 float4 per matrix per stage, 2 per thread.
    int r0 = tid >> 5, c0 = tid & 31;              // idx = tid
    int r1 = (tid + 256) >> 5, c1 = c0;            // idx = tid + 256

    float acc[8][8] = {};

    // Prologue: stage 0
    {
        *(float4*)&As[0][r0][c0 * 4] = *(const float4*)&xb[(size_t)r0 * L + l0 + c0 * 4];
        *(float4*)&As[0][r1][c1 * 4] = *(const float4*)&xb[(size_t)r1 * L + l0 + c1 * 4];
        *(float4*)&Ws[0][r0][c0 * 4] = *(const float4*)&W [(size_t)r0 * D + j0 + c0 * 4];
        *(float4*)&Ws[0][r1][c1 * 4] = *(const float4*)&W [(size_t)r1 * D + j0 + c1 * 4];
    }
    __syncthreads();

    int s = 0;
    for (int kt = 0; kt < D; kt += 16) {
        int ns = s ^ 1;
        if (kt + 16 < D) {
            int kn = kt + 16;
            *(float4*)&As[ns][r0][c0 * 4] = *(const float4*)&xb[(size_t)(kn + r0) * L + l0 + c0 * 4];
            *(float4*)&As[ns][r1][c1 * 4] = *(const float4*)&xb[(size_t)(kn + r1) * L + l0 + c1 * 4];
            *(float4*)&Ws[ns][r0][c0 * 4] = *(const float4*)&W [(size_t)(kn + r0) * D + j0 + c0 * 4];
            *(float4*)&Ws[ns][r1][c1 * 4] = *(const float4*)&W [(size_t)(kn + r1) * D + j0 + c1 * 4];
        }
        #pragma unroll
        for (int kk = 0; kk < 16; kk++) {
            float4 a0 = *(const float4*)&As[s][kk][ty * 4];
            float4 a1 = *(const float4*)&As[s][kk][64 + ty * 4];
            float4 b0 = *(const float4*)&Ws[s][kk][tx * 4];
            float4 b1 = *(const float4*)&Ws[s][kk][64 + tx * 4];
            float av[8] = {a0.x, a0.y, a0.z, a0.w, a1.x, a1.y, a1.z, a1.w};
            float bv[8] = {b0.x, b0.y, b0.z, b0.w, b1.x, b1.y, b1.z, b1.w};
            #pragma unroll
            for (int i = 0; i < 8; i++)
                #pragma unroll
                for (int j = 0; j < 8; j++)
                    acc[i][j] += av[i] * bv[j];
        }
        __syncthreads();
        s = ns;
    }

    float* ob = out + (size_t)b * LP1 * D;
    #pragma unroll
    for (int i = 0; i < 8; i++) {
        int l = l0 + ((i < 4) ? (ty * 4 + i) : (64 + ty * 4 + i - 4));
        float4 v0 = make_float4(acc[i][0], acc[i][1], acc[i][2], acc[i][3]);
        float4 v1 = make_float4(acc[i][4], acc[i][5], acc[i][6], acc[i][7]);
        *(float4*)&ob[(size_t)l * D + j0 + tx * 4]      = v0;
        *(float4*)&ob[(size_t)l * D + j0 + 64 + tx * 4] = v1;
    }
}

// ---------------------------------------------------------------------------
// QKV projection for the relay token (row l = L), input y (B, D).
// grid: (3, B), block: 512
// ---------------------------------------------------------------------------
__global__ void qkv_relay(const float* __restrict__ y,
                          const float* __restrict__ Wq,
                          const float* __restrict__ Wk,
                          const float* __restrict__ Wv) {
    int z = blockIdx.x, b = blockIdx.y;
    const float* W = (z == 0) ? Wq : (z == 1) ? Wk : Wv;
    float* out = (z == 0) ? g_q : (z == 1) ? g_k : g_v;

    __shared__ float sy[D];
    int t = threadIdx.x;
    sy[t] = y[b * D + t];
    __syncthreads();

    float s = 0.f;
    for (int d = 0; d < D; d++) s += sy[d] * W[(size_t)d * D + t];
    out[(size_t)b * LP1 * D + (size_t)L * D + t] = s;
}

// ---------------------------------------------------------------------------
// Local windowed attention: per (b, l) block, warp w = head.
// grid: B*L blocks, 256 threads (8 warps).
// ---------------------------------------------------------------------------
__global__ void local_attn() {
    int m = blockIdx.x;
    int b = m >> 12, l = m & (L - 1);
    int head = threadIdx.x >> 5;
    int lane = threadIdx.x & 31;

    const float* qb = g_q + (size_t)b * LP1 * D;
    const float* kb = g_k + (size_t)b * LP1 * D;
    const float* vb = g_v + (size_t)b * LP1 * D;

    int hoff = head * HD + lane * 2;
    float2 qv = *(const float2*)(qb + (size_t)l * D + hoff);

    float s[4];
    int   lk[4];
    bool  valid[4];
    #pragma unroll
    for (int w = 0; w < 3; w++) {
        lk[w] = l - 1 + w;
        valid[w] = ((unsigned)lk[w] < (unsigned)L);
    }
    lk[3] = L; valid[3] = true;

    #pragma unroll
    for (int w = 0; w < 4; w++) {
        float sv = 0.f;
        if (valid[w]) {
            float2 kv = *(const float2*)(kb + (size_t)lk[w] * D + hoff);
            sv = qv.x * kv.x + qv.y * kv.y;
            #pragma unroll
            for (int o = 16; o > 0; o >>= 1)
                sv += __shfl_xor_sync(0xffffffffu, sv, o);
            sv *= ATT_SCALE;
        }
        s[w] = sv;        // padded key contributes score 0 (matches ref zero-pad)
    }

    float mx = fmaxf(fmaxf(s[0], s[1]), fmaxf(s[2], s[3]));
    float e[4], denom = 0.f;
    #pragma unroll
    for (int w = 0; w < 4; w++) { e[w] = expf(s[w] - mx); denom += e[w]; }
    float inv = 1.f / denom;

    float2 acc = make_float2(0.f, 0.f);
    #pragma unroll
    for (int w = 0; w < 4; w++) {
        if (valid[w]) {
            float2 vv = *(const float2*)(vb + (size_t)lk[w] * D + hoff);
            float a = e[w] * inv;
            acc.x += a * vv.x;
            acc.y += a * vv.y;
        }
    }
    *(float2*)(g_att + ((size_t)b * L + l) * D + hoff) = acc;
}

// ---------------------------------------------------------------------------
// Ring output projection: out[b][e][l] = sum_d WO[d][e] * att[b][l][d] + bO[e]
// C[e][l]: A = WO^T (contiguous e), B = att^T (smem transpose on load).
// 128x128 tile, BK=16, 8x8 per-thread, double-buffered.
// grid: (L/128, D/128, B), 256 threads.
// ---------------------------------------------------------------------------
__global__ void __launch_bounds__(256, 2)
ring_gemm(const float* __restrict__ WO,
          const float* __restrict__ bO,
          float* __restrict__ out) {
    __shared__ float As[2][16][128];   // [d][e]  from WO
    __shared__ float Bs[2][16][132];   // [d][l]  transposed from att (padded)

    int b  = blockIdx.z;
    int l0 = blockIdx.x * 128;
    int e0 = blockIdx.y * 128;
    const float* ab = g_att + (size_t)b * L * D;

    int tid = threadIdx.x;
    int tx = tid & 15, ty = tid >> 4;

    // A loader: same as W loader (row-major, contiguous e)
    int r0 = tid >> 5, c0 = tid & 31;
    int r1 = (tid + 256) >> 5;
    // B loader (transpose): idx -> (li, dq)
    int li0 = tid >> 2,           dq0 = tid & 3;
    int li1 = (tid + 256) >> 2,   dq1 = dq0;

    float acc[8][8] = {};

    // Prologue
    {
        *(float4*)&As[0][r0][c0 * 4] = *(const float4*)&WO[(size_t)r0 * D + e0 + c0 * 4];
        *(float4*)&As[0][r1][c0 * 4] = *(const float4*)&WO[(size_t)r1 * D + e0 + c0 * 4];
        float4 v0 = *(const float4*)&ab[(size_t)(l0 + li0) * D + dq0 * 4];
        float4 v1 = *(const float4*)&ab[(size_t)(l0 + li1) * D + dq1 * 4];
        Bs[0][dq0 * 4 + 0][li0] = v0.x; Bs[0][dq0 * 4 + 1][li0] = v0.y;
        Bs[0][dq0 * 4 + 2][li0] = v0.z; Bs[0][dq0 * 4 + 3][li0] = v0.w;
        Bs[0][dq1 * 4 + 0][li1] = v1.x; Bs[0][dq1 * 4 + 1][li1] = v1.y;
        Bs[0][dq1 * 4 + 2][li1] = v1.z; Bs[0][dq1 * 4 + 3][li1] = v1.w;
    }
    __syncthreads();

    int s = 0;
    for (int kt = 0; kt < D; kt += 16) {
        int ns = s ^ 1;
        if (kt + 16 < D) {
            int kn = kt + 16;
            *(float4*)&As[ns][r0][c0 * 4] = *(const float4*)&WO[(size_t)(kn + r0) * D + e0 + c0 * 4];
            *(float4*)&As[ns][r1][c0 * 4] = *(const float4*)&WO[(size_t)(kn + r1) * D + e0 + c0 * 4];
            float4 v0 = *(const float4*)&ab[(size_t)(l0 + li0) * D + kn + dq0 * 4];
            float4 v1 = *(const float4*)&ab[(size_t)(l0 + li1) * D + kn + dq1 * 4];
            Bs[ns][dq0 * 4 + 0][li0] = v0.x; Bs[ns][dq0 * 4 + 1][li0] = v0.y;
            Bs[ns][dq0 * 4 + 2][li0] = v0.z; Bs[ns][dq0 * 4 + 3][li0] = v0.w;
            Bs[ns][dq1 * 4 + 0][li1] = v1.x; Bs[ns][dq1 * 4 + 1][li1] = v1.y;
            Bs[ns][dq1 * 4 + 2][li1] = v1.z; Bs[ns][dq1 * 4 + 3][li1] = v1.w;
        }
        #pragma unroll
        for (int kk = 0; kk < 16; kk++) {
            float4 a0 = *(const float4*)&As[s][kk][ty * 4];
            float4 a1 = *(const float4*)&As[s][kk][64 + ty * 4];
            float4 b0 = *(const float4*)&Bs[s][kk][tx * 4];
            float4 b1 = *(const float4*)&Bs[s][kk][64 + tx * 4];
            float av[8] = {a0.x, a0.y, a0.z, a0.w, a1.x, a1.y, a1.z, a1.w};
            float bv[8] = {b0.x, b0.y, b0.z, b0.w, b1.x, b1.y, b1.z, b1.w};
            #pragma unroll
            for (int i = 0; i < 8; i++)
                #pragma unroll
                for (int j = 0; j < 8; j++)
                    acc[i][j] += av[i] * bv[j];
        }
        __syncthreads();
        s = ns;
    }

    float* outb = out + (size_t)b * D * L;
    #pragma unroll
    for (int i = 0; i < 8; i++) {
        int e = e0 + ((i < 4) ? (ty * 4 + i) : (64 + ty * 4 + i - 4));
        float bias = bO[e];
        float4 v0 = make_float4(acc[i][0] + bias, acc[i][1] + bias,
                                acc[i][2] + bias, acc[i][3] + bias);
        float4 v1 = make_float4(acc[i][4] + bias, acc[i][5] + bias,
                                acc[i][6] + bias, acc[i][7] + bias);
        *(float4*)&outb[(size_t)e * L + l0 + tx * 4]      = v0;
        *(float4*)&outb[(size_t)e * L + l0 + 64 + tx * 4] = v1;
    }
}

// ---------------------------------------------------------------------------
// Relay attention: relay query attends over all L+1 keys of its head.
// grid: (NH, B), 256 threads.
// ---------------------------------------------------------------------------
__global__ void relay_attn() {
    int n = blockIdx.x, b = blockIdx.y;
    __shared__ float sq[HD];
    __shared__ float sc[LP1];
    __shared__ float red[256];
    __shared__ float pacc[4][64];

    int tid = threadIdx.x;
    const float* qb = g_q + (size_t)b * LP1 * D;
    const float* kb = g_k + (size_t)b * LP1 * D;
    const float* vb = g_v + (size_t)b * LP1 * D;
    int hoff = n * HD;

    if (tid < HD) sq[tid] = qb[(size_t)L * D + hoff + tid];
    __syncthreads();

    float lmax = -1e30f;
    for (int l = tid; l < LP1; l += 256) {
        const float* kr = kb + (size_t)l * D + hoff;
        float dot = 0.f;
        #pragma unroll 8
        for (int d = 0; d < HD; d++) dot += sq[d] * kr[d];
        dot *= ATT_SCALE;
        sc[l] = dot;
        lmax = fmaxf(lmax, dot);
    }
    red[tid] = lmax; __syncthreads();
    for (int s = 128; s > 0; s >>= 1) {
        if (tid < s) red[tid] = fmaxf(red[tid], red[tid + s]);
        __syncthreads();
    }
    float mx = red[0];
    __syncthreads();

    float lsum = 0.f;
    for (int l = tid; l < LP1; l += 256) {
        float e = expf(sc[l] - mx);
        sc[l] = e;
        lsum += e;
    }
    red[tid] = lsum; __syncthreads();
    for (int s = 128; s > 0; s >>= 1) {
        if (tid < s) red[tid] += red[tid + s];
        __syncthreads();
    }
    float inv = 1.f / red[0];
    __syncthreads();

    int d = tid & 63, g = tid >> 6;
    float part = 0.f;
    for (int l = g; l < LP1; l += 4)
        part += sc[l] * vb[(size_t)l * D + hoff + d];
    pacc[g][d] = part;
    __syncthreads();
    if (tid < 64) {
        float tot = (pacc[0][tid] + pacc[1][tid] + pacc[2][tid] + pacc[3][tid]) * inv;
        g_attr[b * D + hoff + tid] = tot;
    }
}

// ---------------------------------------------------------------------------
// Relay output projection.
// grid: B, block: 512.
// ---------------------------------------------------------------------------
__global__ void relay_out(const float* __restrict__ WOs,
                          const float* __restrict__ bOs,
                          float* __restrict__ out) {
    int b = blockIdx.x;
    __shared__ float sa[D];
    int t = threadIdx.x;
    sa[t] = g_attr[b * D + t];
    __syncthreads();
    float s = bOs[t];
    for (int d = 0; d < D; d++) s += sa[d] * WOs[(size_t)d * D + t];
    out[(size_t)B * D * L + b * D + t] = s;
}

// ---------------------------------------------------------------------------
extern "C" void kernel_launch(void* const* d_in, const int* in_sizes, int n_in,
                              void* d_out, int out_size) {
    const float* x       = (const float*)d_in[0];
    const float* y       = (const float*)d_in[1];
    const float* Wq      = (const float*)d_in[2];
    const float* Wk      = (const float*)d_in[3];
    const float* Wv      = (const float*)d_in[4];
    const float* WO_ring = (const float*)d_in[5];
    const float* bO_ring = (const float*)d_in[6];
    const float* WO_star = (const float*)d_in[7];
    const float* bO_star = (const float*)d_in[8];
    float* out = (float*)d_out;

    qkv_gemm <<<dim3(B * L / 128, D / 128, 3), 256>>>(x, Wq, Wk, Wv);
    qkv_relay<<<dim3(3, B), D>>>(y, Wq, Wk, Wv);
    local_attn<<<B * L, 256>>>();
    ring_gemm<<<dim3(L / 128, D / 128, B), 256>>>(WO_ring, bO_ring, out);
    relay_attn<<<dim3(NH, B), 256>>>();
    relay_out<<<B, D>>>(WO_star, bO_star, out);
}

// round 6
// speedup vs baseline: 2.4797x; 1.7578x over previous
#include <cuda_runtime.h>
#include <cstdint>

#define B   8
#define D   512
#define L   4096
#define NH  8
#define HD  64
#define LP1 4097
#define ATT_SCALE 0.125f   // 1/sqrt(64)

// Scratch (device globals: no runtime allocation allowed)
__device__ float g_q[B * LP1 * D];
__device__ float g_k[B * LP1 * D];
__device__ float g_v[B * LP1 * D];
__device__ float g_att[B * L * D];   // (b, l, d) row-major
__device__ float g_attr[B * D];

// ---------------------------------------------------------------------------
// TF32 helpers
// ---------------------------------------------------------------------------
__device__ __forceinline__ unsigned f2t(float f) {
    unsigned r;
    asm("cvt.rna.tf32.f32 %0, %1;" : "=r"(r) : "f"(f));
    return r;
}

__device__ __forceinline__ void mma_tf32(float c[4], const unsigned a[4],
                                         const unsigned b[2]) {
    asm volatile(
        "mma.sync.aligned.m16n8k8.row.col.f32.tf32.tf32.f32 "
        "{%0,%1,%2,%3}, {%4,%5,%6,%7}, {%8,%9}, {%0,%1,%2,%3};"
        : "+f"(c[0]), "+f"(c[1]), "+f"(c[2]), "+f"(c[3])
        : "r"(a[0]), "r"(a[1]), "r"(a[2]), "r"(a[3]), "r"(b[0]), "r"(b[1]));
}

#define SPAD 136   // smem row pad: frag-load banks (8*tg + g) % 32 all distinct

// ---------------------------------------------------------------------------
// QKV projection (TF32 tensor cores).
//   out[b][l][j] = sum_d x[b][d][l] * W[d][j]
// 128x128 tile, BK=16, 256 threads (8 warps: 2m x 4n, 64x32 per warp),
// m16n8k8 TF32 mma, double-buffered smem.
// grid: (B*L/128, D/128, 3)
// ---------------------------------------------------------------------------
__global__ void __launch_bounds__(256, 2)
qkv_gemm(const float* __restrict__ x,
         const float* __restrict__ Wq,
         const float* __restrict__ Wk,
         const float* __restrict__ Wv) {
    __shared__ unsigned As[2][16][SPAD];   // [k][m=l]
    __shared__ unsigned Ws[2][16][SPAD];   // [k][n=j]

    int z = blockIdx.z;
    const float* W = (z == 0) ? Wq : (z == 1) ? Wk : Wv;
    float* out = (z == 0) ? g_q : (z == 1) ? g_k : g_v;

    int m0 = blockIdx.x * 128;
    int b  = m0 >> 12;
    int l0 = m0 & (L - 1);
    int j0 = blockIdx.y * 128;

    const float* xb = x + (size_t)b * D * L;
    int tid  = threadIdx.x;
    int lane = tid & 31, wid = tid >> 5;
    int g    = lane >> 2, tg = lane & 3;
    int wm   = wid & 1,  wn = wid >> 1;

    // Loader mapping: warp w loads rows r0=w and r1=w+8, lane covers 4 cols.
    int r0 = wid, r1 = wid + 8, c4 = lane * 4;

    float acc[4][4][4] = {};

    // Prologue: stage 0
    {
        float4 a0 = *(const float4*)&xb[(size_t)r0 * L + l0 + c4];
        float4 a1 = *(const float4*)&xb[(size_t)r1 * L + l0 + c4];
        float4 w0 = *(const float4*)&W [(size_t)r0 * D + j0 + c4];
        float4 w1 = *(const float4*)&W [(size_t)r1 * D + j0 + c4];
        *(uint4*)&As[0][r0][c4] = make_uint4(f2t(a0.x), f2t(a0.y), f2t(a0.z), f2t(a0.w));
        *(uint4*)&As[0][r1][c4] = make_uint4(f2t(a1.x), f2t(a1.y), f2t(a1.z), f2t(a1.w));
        *(uint4*)&Ws[0][r0][c4] = make_uint4(f2t(w0.x), f2t(w0.y), f2t(w0.z), f2t(w0.w));
        *(uint4*)&Ws[0][r1][c4] = make_uint4(f2t(w1.x), f2t(w1.y), f2t(w1.z), f2t(w1.w));
    }
    __syncthreads();

    int s = 0;
    for (int kt = 0; kt < D; kt += 16) {
        int ns = s ^ 1;
        if (kt + 16 < D) {
            int kn = kt + 16;
            float4 a0 = *(const float4*)&xb[(size_t)(kn + r0) * L + l0 + c4];
            float4 a1 = *(const float4*)&xb[(size_t)(kn + r1) * L + l0 + c4];
            float4 w0 = *(const float4*)&W [(size_t)(kn + r0) * D + j0 + c4];
            float4 w1 = *(const float4*)&W [(size_t)(kn + r1) * D + j0 + c4];
            *(uint4*)&As[ns][r0][c4] = make_uint4(f2t(a0.x), f2t(a0.y), f2t(a0.z), f2t(a0.w));
            *(uint4*)&As[ns][r1][c4] = make_uint4(f2t(a1.x), f2t(a1.y), f2t(a1.z), f2t(a1.w));
            *(uint4*)&Ws[ns][r0][c4] = make_uint4(f2t(w0.x), f2t(w0.y), f2t(w0.z), f2t(w0.w));
            *(uint4*)&Ws[ns][r1][c4] = make_uint4(f2t(w1.x), f2t(w1.y), f2t(w1.z), f2t(w1.w));
        }
        #pragma unroll
        for (int ks = 0; ks < 2; ks++) {
            int k0 = ks * 8;
            unsigned afr[4][4], bfr[4][2];
            #pragma unroll
            for (int mt = 0; mt < 4; mt++) {
                int m = wm * 64 + mt * 16 + g;
                afr[mt][0] = As[s][k0 + tg    ][m];
                afr[mt][1] = As[s][k0 + tg    ][m + 8];
                afr[mt][2] = As[s][k0 + tg + 4][m];
                afr[mt][3] = As[s][k0 + tg + 4][m + 8];
            }
            #pragma unroll
            for (int nt = 0; nt < 4; nt++) {
                int n = wn * 32 + nt * 8 + g;
                bfr[nt][0] = Ws[s][k0 + tg    ][n];
                bfr[nt][1] = Ws[s][k0 + tg + 4][n];
            }
            #pragma unroll
            for (int mt = 0; mt < 4; mt++)
                #pragma unroll
                for (int nt = 0; nt < 4; nt++)
                    mma_tf32(acc[mt][nt], afr[mt], bfr[nt]);
        }
        __syncthreads();
        s = ns;
    }

    float* ob = out + (size_t)b * LP1 * D;
    #pragma unroll
    for (int mt = 0; mt < 4; mt++) {
        int row0 = l0 + wm * 64 + mt * 16 + g;
        #pragma unroll
        for (int nt = 0; nt < 4; nt++) {
            int col = j0 + wn * 32 + nt * 8 + tg * 2;
            *(float2*)&ob[(size_t)row0 * D + col] =
                make_float2(acc[mt][nt][0], acc[mt][nt][1]);
            *(float2*)&ob[(size_t)(row0 + 8) * D + col] =
                make_float2(acc[mt][nt][2], acc[mt][nt][3]);
        }
    }
}

// ---------------------------------------------------------------------------
// QKV projection for the relay token (fp32, tiny).
// grid: (3, B), block: 512
// ---------------------------------------------------------------------------
__global__ void qkv_relay(const float* __restrict__ y,
                          const float* __restrict__ Wq,
                          const float* __restrict__ Wk,
                          const float* __restrict__ Wv) {
    int z = blockIdx.x, b = blockIdx.y;
    const float* W = (z == 0) ? Wq : (z == 1) ? Wk : Wv;
    float* out = (z == 0) ? g_q : (z == 1) ? g_k : g_v;

    __shared__ float sy[D];
    int t = threadIdx.x;
    sy[t] = y[b * D + t];
    __syncthreads();

    float s = 0.f;
    for (int d = 0; d < D; d++) s += sy[d] * W[(size_t)d * D + t];
    out[(size_t)b * LP1 * D + (size_t)L * D + t] = s;
}

// ---------------------------------------------------------------------------
// Local windowed attention: per (b, l) block, warp w = head.
// grid: B*L blocks, 256 threads (8 warps).
// ---------------------------------------------------------------------------
__global__ void local_attn() {
    int m = blockIdx.x;
    int b = m >> 12, l = m & (L - 1);
    int head = threadIdx.x >> 5;
    int lane = threadIdx.x & 31;

    const float* qb = g_q + (size_t)b * LP1 * D;
    const float* kb = g_k + (size_t)b * LP1 * D;
    const float* vb = g_v + (size_t)b * LP1 * D;

    int hoff = head * HD + lane * 2;
    float2 qv = *(const float2*)(qb + (size_t)l * D + hoff);

    float s[4];
    int   lk[4];
    bool  valid[4];
    #pragma unroll
    for (int w = 0; w < 3; w++) {
        lk[w] = l - 1 + w;
        valid[w] = ((unsigned)lk[w] < (unsigned)L);
    }
    lk[3] = L; valid[3] = true;

    #pragma unroll
    for (int w = 0; w < 4; w++) {
        float sv = 0.f;
        if (valid[w]) {
            float2 kv = *(const float2*)(kb + (size_t)lk[w] * D + hoff);
            sv = qv.x * kv.x + qv.y * kv.y;
            #pragma unroll
            for (int o = 16; o > 0; o >>= 1)
                sv += __shfl_xor_sync(0xffffffffu, sv, o);
            sv *= ATT_SCALE;
        }
        s[w] = sv;        // padded key contributes score 0 (matches ref zero-pad)
    }

    float mx = fmaxf(fmaxf(s[0], s[1]), fmaxf(s[2], s[3]));
    float e[4], denom = 0.f;
    #pragma unroll
    for (int w = 0; w < 4; w++) { e[w] = expf(s[w] - mx); denom += e[w]; }
    float inv = 1.f / denom;

    float2 acc = make_float2(0.f, 0.f);
    #pragma unroll
    for (int w = 0; w < 4; w++) {
        if (valid[w]) {
            float2 vv = *(const float2*)(vb + (size_t)lk[w] * D + hoff);
            float a = e[w] * inv;
            acc.x += a * vv.x;
            acc.y += a * vv.y;
        }
    }
    *(float2*)(g_att + ((size_t)b * L + l) * D + hoff) = acc;
}

// ---------------------------------------------------------------------------
// Ring output projection (TF32): out[b][e][l] = sum_d WO[d][e]*att[b][l][d]+bO[e]
// C rows = e (m), cols = l (n). A = WO (k-major over d, contiguous e),
// B = att transposed into smem [d][l].
// grid: (L/128, D/128, B), 256 threads.
// ---------------------------------------------------------------------------
__global__ void __launch_bounds__(256, 2)
ring_gemm(const float* __restrict__ WO,
          const float* __restrict__ bO,
          float* __restrict__ out) {
    __shared__ unsigned As[2][16][SPAD];   // [k=d][m=e]  from WO
    __shared__ unsigned Bs[2][16][SPAD];   // [k=d][n=l]  transposed from att

    int b  = blockIdx.z;
    int l0 = blockIdx.x * 128;
    int e0 = blockIdx.y * 128;
    const float* ab = g_att + (size_t)b * L * D;

    int tid  = threadIdx.x;
    int lane = tid & 31, wid = tid >> 5;
    int g    = lane >> 2, tg = lane & 3;
    int wm   = wid & 1,  wn = wid >> 1;

    int r0 = wid, r1 = wid + 8, c4 = lane * 4;
    // B transpose loader: li over l, dq over d-quads
    int li0 = tid >> 2, li1 = li0 + 64, dq = tid & 3;

    float acc[4][4][4] = {};

    // Prologue
    {
        float4 w0 = *(const float4*)&WO[(size_t)r0 * D + e0 + c4];
        float4 w1 = *(const float4*)&WO[(size_t)r1 * D + e0 + c4];
        *(uint4*)&As[0][r0][c4] = make_uint4(f2t(w0.x), f2t(w0.y), f2t(w0.z), f2t(w0.w));
        *(uint4*)&As[0][r1][c4] = make_uint4(f2t(w1.x), f2t(w1.y), f2t(w1.z), f2t(w1.w));
        float4 v0 = *(const float4*)&ab[(size_t)(l0 + li0) * D + dq * 4];
        float4 v1 = *(const float4*)&ab[(size_t)(l0 + li1) * D + dq * 4];
        Bs[0][dq * 4 + 0][li0] = f2t(v0.x); Bs[0][dq * 4 + 1][li0] = f2t(v0.y);
        Bs[0][dq * 4 + 2][li0] = f2t(v0.z); Bs[0][dq * 4 + 3][li0] = f2t(v0.w);
        Bs[0][dq * 4 + 0][li1] = f2t(v1.x); Bs[0][dq * 4 + 1][li1] = f2t(v1.y);
        Bs[0][dq * 4 + 2][li1] = f2t(v1.z); Bs[0][dq * 4 + 3][li1] = f2t(v1.w);
    }
    __syncthreads();

    int s = 0;
    for (int kt = 0; kt < D; kt += 16) {
        int ns = s ^ 1;
        if (kt + 16 < D) {
            int kn = kt + 16;
            float4 w0 = *(const float4*)&WO[(size_t)(kn + r0) * D + e0 + c4];
            float4 w1 = *(const float4*)&WO[(size_t)(kn + r1) * D + e0 + c4];
            *(uint4*)&As[ns][r0][c4] = make_uint4(f2t(w0.x), f2t(w0.y), f2t(w0.z), f2t(w0.w));
            *(uint4*)&As[ns][r1][c4] = make_uint4(f2t(w1.x), f2t(w1.y), f2t(w1.z), f2t(w1.w));
            float4 v0 = *(const float4*)&ab[(size_t)(l0 + li0) * D + kn + dq * 4];
            float4 v1 = *(const float4*)&ab[(size_t)(l0 + li1) * D + kn + dq * 4];
            Bs[ns][dq * 4 + 0][li0] = f2t(v0.x); Bs[ns][dq * 4 + 1][li0] = f2t(v0.y);
            Bs[ns][dq * 4 + 2][li0] = f2t(v0.z); Bs[ns][dq * 4 + 3][li0] = f2t(v0.w);
            Bs[ns][dq * 4 + 0][li1] = f2t(v1.x); Bs[ns][dq * 4 + 1][li1] = f2t(v1.y);
            Bs[ns][dq * 4 + 2][li1] = f2t(v1.z); Bs[ns][dq * 4 + 3][li1] = f2t(v1.w);
        }
        #pragma unroll
        for (int ks = 0; ks < 2; ks++) {
            int k0 = ks * 8;
            unsigned afr[4][4], bfr[4][2];
            #pragma unroll
            for (int mt = 0; mt < 4; mt++) {
                int m = wm * 64 + mt * 16 + g;
                afr[mt][0] = As[s][k0 + tg    ][m];
                afr[mt][1] = As[s][k0 + tg    ][m + 8];
                afr[mt][2] = As[s][k0 + tg + 4][m];
                afr[mt][3] = As[s][k0 + tg + 4][m + 8];
            }
            #pragma unroll
            for (int nt = 0; nt < 4; nt++) {
                int n = wn * 32 + nt * 8 + g;
                bfr[nt][0] = Bs[s][k0 + tg    ][n];
                bfr[nt][1] = Bs[s][k0 + tg + 4][n];
            }
            #pragma unroll
            for (int mt = 0; mt < 4; mt++)
                #pragma unroll
                for (int nt = 0; nt < 4; nt++)
                    mma_tf32(acc[mt][nt], afr[mt], bfr[nt]);
        }
        __syncthreads();
        s = ns;
    }

    float* outb = out + (size_t)b * D * L;
    #pragma unroll
    for (int mt = 0; mt < 4; mt++) {
        int e = e0 + wm * 64 + mt * 16 + g;
        float bias0 = bO[e];
        float bias1 = bO[e + 8];
        #pragma unroll
        for (int nt = 0; nt < 4; nt++) {
            int col = l0 + wn * 32 + nt * 8 + tg * 2;
            *(float2*)&outb[(size_t)e * L + col] =
                make_float2(acc[mt][nt][0] + bias0, acc[mt][nt][1] + bias0);
            *(float2*)&outb[(size_t)(e + 8) * L + col] =
                make_float2(acc[mt][nt][2] + bias1, acc[mt][nt][3] + bias1);
        }
    }
}

// ---------------------------------------------------------------------------
// Relay attention: relay query attends over all L+1 keys of its head.
// grid: (NH, B), 256 threads.
// ---------------------------------------------------------------------------
__global__ void relay_attn() {
    int n = blockIdx.x, b = blockIdx.y;
    __shared__ float sq[HD];
    __shared__ float sc[LP1];
    __shared__ float red[256];
    __shared__ float pacc[4][64];

    int tid = threadIdx.x;
    const float* qb = g_q + (size_t)b * LP1 * D;
    const float* kb = g_k + (size_t)b * LP1 * D;
    const float* vb = g_v + (size_t)b * LP1 * D;
    int hoff = n * HD;

    if (tid < HD) sq[tid] = qb[(size_t)L * D + hoff + tid];
    __syncthreads();

    float lmax = -1e30f;
    for (int l = tid; l < LP1; l += 256) {
        const float* kr = kb + (size_t)l * D + hoff;
        float dot = 0.f;
        #pragma unroll 8
        for (int d = 0; d < HD; d++) dot += sq[d] * kr[d];
        dot *= ATT_SCALE;
        sc[l] = dot;
        lmax = fmaxf(lmax, dot);
    }
    red[tid] = lmax; __syncthreads();
    for (int s = 128; s > 0; s >>= 1) {
        if (tid < s) red[tid] = fmaxf(red[tid], red[tid + s]);
        __syncthreads();
    }
    float mx = red[0];
    __syncthreads();

    float lsum = 0.f;
    for (int l = tid; l < LP1; l += 256) {
        float e = expf(sc[l] - mx);
        sc[l] = e;
        lsum += e;
    }
    red[tid] = lsum; __syncthreads();
    for (int s = 128; s > 0; s >>= 1) {
        if (tid < s) red[tid] += red[tid + s];
        __syncthreads();
    }
    float inv = 1.f / red[0];
    __syncthreads();

    int d = tid & 63, g = tid >> 6;
    float part = 0.f;
    for (int l = g; l < LP1; l += 4)
        part += sc[l] * vb[(size_t)l * D + hoff + d];
    pacc[g][d] = part;
    __syncthreads();
    if (tid < 64) {
        float tot = (pacc[0][tid] + pacc[1][tid] + pacc[2][tid] + pacc[3][tid]) * inv;
        g_attr[b * D + hoff + tid] = tot;
    }
}

// ---------------------------------------------------------------------------
// Relay output projection.
// grid: B, block: 512.
// ---------------------------------------------------------------------------
__global__ void relay_out(const float* __restrict__ WOs,
                          const float* __restrict__ bOs,
                          float* __restrict__ out) {
    int b = blockIdx.x;
    __shared__ float sa[D];
    int t = threadIdx.x;
    sa[t] = g_attr[b * D + t];
    __syncthreads();
    float s = bOs[t];
    for (int d = 0; d < D; d++) s += sa[d] * WOs[(size_t)d * D + t];
    out[(size_t)B * D * L + b * D + t] = s;
}

// ---------------------------------------------------------------------------
extern "C" void kernel_launch(void* const* d_in, const int* in_sizes, int n_in,
                              void* d_out, int out_size) {
    const float* x       = (const float*)d_in[0];
    const float* y       = (const float*)d_in[1];
    const float* Wq      = (const float*)d_in[2];
    const float* Wk      = (const float*)d_in[3];
    const float* Wv      = (const float*)d_in[4];
    const float* WO_ring = (const float*)d_in[5];
    const float* bO_ring = (const float*)d_in[6];
    const float* WO_star = (const float*)d_in[7];
    const float* bO_star = (const float*)d_in[8];
    float* out = (float*)d_out;

    qkv_gemm <<<dim3(B * L / 128, D / 128, 3), 256>>>(x, Wq, Wk, Wv);
    qkv_relay<<<dim3(3, B), D>>>(y, Wq, Wk, Wv);
    local_attn<<<B * L, 256>>>();
    ring_gemm<<<dim3(L / 128, D / 128, B), 256>>>(WO_ring, bO_ring, out);
    relay_attn<<<dim3(NH, B), 256>>>();
    relay_out<<<B, D>>>(WO_star, bO_star, out);
}